// round 8
// baseline (speedup 1.0000x reference)
#include <cuda_runtime.h>
#include <cuda_bf16.h>
#include <cstdint>

// YOLOv5 detect head, unified bf16 HMMA kernel for all three scales.
// CTA tile 128m x 128n, K chunks of 32, double-buffered SMEM, distance-2
// register prefetch pipeline, ldmatrix.x4 fragments (row stride 5 units,
// conflict-free), SMEM-staged coalesced decode epilogue.

#define ROWU 5
#define BUFU (128 * ROWU)        // 640 uint4 per buffer
#define BUFBYTES (BUFU * 16)     // 10240
#define OFF_B 20480
#define OFF_BIAS 40960
#define OFF_ANC 41984
#define STG_STRIDE 69            // stage row stride (floats); 5g+2t injective -> no conflicts

__device__ __forceinline__ uint32_t smem_u32(const void* p) {
    uint32_t a;
    asm("{ .reg .u64 t; cvta.to.shared.u64 t, %1; cvt.u32.u64 %0, t; }"
        : "=r"(a) : "l"(p));
    return a;
}
__device__ __forceinline__ uint32_t pack2(float a, float b) {
    __nv_bfloat162 h = __floats2bfloat162_rn(a, b);
    return *reinterpret_cast<uint32_t*>(&h);
}

__global__ __launch_bounds__(256, 2)
void yolo_all_kernel(const float* __restrict__ p0, const float* __restrict__ p1,
                     const float* __restrict__ p2,
                     const float* __restrict__ w0, const float* __restrict__ w1,
                     const float* __restrict__ w2,
                     const float* __restrict__ bb0, const float* __restrict__ bb1,
                     const float* __restrict__ bb2,
                     const float* __restrict__ anchors,
                     float* __restrict__ out,
                     int bs, int t2, int t1)
{
    __shared__ __align__(16) char raw[42048];
    uint4* AsmP   = reinterpret_cast<uint4*>(raw);
    uint4* BsmP   = reinterpret_cast<uint4*>(raw + OFF_B);
    float* bias_s = reinterpret_cast<float*>(raw + OFF_BIAS);
    float* anc_s  = reinterpret_cast<float*>(raw + OFF_ANC);
    float* stage  = reinterpret_cast<float*>(raw);   // reused after mainloop

    const int tid  = threadIdx.x;
    const int lane = tid & 31;
    const int wid  = tid >> 5;
    const int wm   = wid >> 2;     // 0..1
    const int wn   = wid & 3;      // 0..3
    const int gid  = lane >> 2;    // 0..7
    const int tig  = lane & 3;     // 0..3

    // ---- scale dispatch (scale 2 first: deepest K) ----
    int bid = blockIdx.x;
    const float *p, *wmat, *bi, *anc;
    int C, S, nx, row_off;
    float strd;
    if (bid < 2 * t2) {
        p = p2; wmat = w2; bi = bb2; anc = anchors + 12;
        C = 1024; S = 400; nx = 20; strd = 32.f; row_off = 24000;
    } else if (bid < 2 * (t2 + t1)) {
        bid -= 2 * t2;
        p = p1; wmat = w1; bi = bb1; anc = anchors + 6;
        C = 512; S = 1600; nx = 40; strd = 16.f; row_off = 19200;
    } else {
        bid -= 2 * (t2 + t1);
        p = p0; wmat = w0; bi = bb0; anc = anchors;
        C = 256; S = 6400; nx = 80; strd = 8.f; row_off = 0;
    }
    const int m0   = (bid >> 1) << 7;
    const int n0   = (bid & 1) << 7;
    const int Mtot = bs * S;

    if (tid < 255) bias_s[tid] = bi[tid];
    if (tid < 6)   anc_s[tid]  = anc[tid];

    // ---- producer mappings ----
    const int arow = tid & 127;
    const int au   = tid >> 7;                 // units au, au+2
    int am = m0 + arow; if (am >= Mtot) am = Mtot - 1;
    const int ab  = am / S;
    const int as_ = am - ab * S;
    const float* abase = p + (size_t)ab * (size_t)C * (size_t)S + (size_t)as_;

    const int brow = tid & 127;
    const int buu  = tid >> 7;
    const int bng  = n0 + brow;
    const float* bbase = (bng < 255) ? (wmat + (size_t)bng * (size_t)C) : nullptr;

    // ---- loop-invariant ldmatrix addresses ----
    const uint32_t a_sm0 = smem_u32(AsmP);
    const uint32_t b_sm0 = smem_u32(BsmP);
    const int l8 = lane & 7, lg = lane >> 3;
    uint32_t aAddr[4], bAddr[2];
    #pragma unroll
    for (int mt = 0; mt < 4; mt++)
        aAddr[mt] = a_sm0 + ((((wm * 64 + mt * 16 + (lg & 1) * 8 + l8) * ROWU) + (lg >> 1)) << 4);
    #pragma unroll
    for (int pr = 0; pr < 2; pr++)
        bAddr[pr] = b_sm0 + ((((wn * 32 + pr * 16 + (lg >> 1) * 8 + l8) * ROWU) + (lg & 1)) << 4);

    float acc[4][4][4] = {};
    const int nk = C >> 5;

    uint32_t ra[8], rb[8];
    auto loadA = [&](int k0, uint32_t* r) {
        #pragma unroll
        for (int uu = 0; uu < 2; uu++) {
            const int u = au + uu * 2;
            const float* q = abase + (size_t)(k0 + u * 8) * (size_t)S;
            r[uu * 4 + 0] = pack2(q[0],                 q[(size_t)S]);
            r[uu * 4 + 1] = pack2(q[2 * (size_t)S],     q[3 * (size_t)S]);
            r[uu * 4 + 2] = pack2(q[4 * (size_t)S],     q[5 * (size_t)S]);
            r[uu * 4 + 3] = pack2(q[6 * (size_t)S],     q[7 * (size_t)S]);
        }
    };
    auto loadB = [&](int k0, uint32_t* r) {
        #pragma unroll
        for (int uu = 0; uu < 2; uu++) {
            const int u = buu + uu * 2;
            if (bbase) {
                float4 x = *reinterpret_cast<const float4*>(bbase + k0 + u * 8);
                float4 y = *reinterpret_cast<const float4*>(bbase + k0 + u * 8 + 4);
                r[uu * 4 + 0] = pack2(x.x, x.y); r[uu * 4 + 1] = pack2(x.z, x.w);
                r[uu * 4 + 2] = pack2(y.x, y.y); r[uu * 4 + 3] = pack2(y.z, y.w);
            } else {
                r[uu * 4 + 0] = 0u; r[uu * 4 + 1] = 0u;
                r[uu * 4 + 2] = 0u; r[uu * 4 + 3] = 0u;
            }
        }
    };
    auto stsAB = [&](const uint32_t* xa, const uint32_t* xb, int nb) {
        #pragma unroll
        for (int uu = 0; uu < 2; uu++) {
            AsmP[nb * BUFU + arow * ROWU + (au + uu * 2)] =
                make_uint4(xa[uu * 4], xa[uu * 4 + 1], xa[uu * 4 + 2], xa[uu * 4 + 3]);
            BsmP[nb * BUFU + brow * ROWU + (buu + uu * 2)] =
                make_uint4(xb[uu * 4], xb[uu * 4 + 1], xb[uu * 4 + 2], xb[uu * 4 + 3]);
        }
    };

    // ---- prologue ----
    {
        uint32_t ta[8], tb[8];
        loadA(0, ta); loadB(0, tb);
        stsAB(ta, tb, 0);
    }
    if (nk > 1) { loadA(32, ra); loadB(32, rb); }
    __syncthreads();

    // ---- main loop (distance-2 pipeline) ----
    for (int it = 0; it < nk; ++it) {
        const int buf = it & 1;
        const uint32_t boff = (uint32_t)buf * BUFBYTES;
        if (it + 1 < nk) stsAB(ra, rb, buf ^ 1);
        if (it + 2 < nk) { loadA((it + 2) << 5, ra); loadB((it + 2) << 5, rb); }

        #pragma unroll
        for (int ks = 0; ks < 2; ks++) {
            uint32_t af[4][4], bf[2][4];
            #pragma unroll
            for (int mt = 0; mt < 4; mt++)
                asm volatile("ldmatrix.sync.aligned.m8n8.x4.shared.b16 {%0,%1,%2,%3}, [%4];"
                             : "=r"(af[mt][0]), "=r"(af[mt][1]), "=r"(af[mt][2]), "=r"(af[mt][3])
                             : "r"(aAddr[mt] + boff + ks * 32));
            #pragma unroll
            for (int pr = 0; pr < 2; pr++)
                asm volatile("ldmatrix.sync.aligned.m8n8.x4.shared.b16 {%0,%1,%2,%3}, [%4];"
                             : "=r"(bf[pr][0]), "=r"(bf[pr][1]), "=r"(bf[pr][2]), "=r"(bf[pr][3])
                             : "r"(bAddr[pr] + boff + ks * 32));
            #pragma unroll
            for (int mt = 0; mt < 4; mt++)
                #pragma unroll
                for (int nt = 0; nt < 4; nt++)
                    asm volatile(
                        "mma.sync.aligned.m16n8k16.row.col.f32.bf16.bf16.f32 "
                        "{%0,%1,%2,%3}, {%4,%5,%6,%7}, {%8,%9}, {%0,%1,%2,%3};"
                        : "+f"(acc[mt][nt][0]), "+f"(acc[mt][nt][1]),
                          "+f"(acc[mt][nt][2]), "+f"(acc[mt][nt][3])
                        : "r"(af[mt][0]), "r"(af[mt][1]), "r"(af[mt][2]), "r"(af[mt][3]),
                          "r"(bf[nt >> 1][(nt & 1) * 2]), "r"(bf[nt >> 1][(nt & 1) * 2 + 1]));
        }
        __syncthreads();
    }

    // ---- epilogue: SMEM-staged coalesced decode ----
    const float aw[3] = { anc_s[0], anc_s[2], anc_s[4] };
    const float ah[3] = { anc_s[1], anc_s[3], anc_s[5] };
    const size_t sS85 = (size_t)S * 85u;
    const int total_rows = 25200;

    #pragma unroll
    for (int h = 0; h < 2; h++) {
        // stage: warp wn's 16-col half (nt = 2h, 2h+1) -> stage cols wn*16 + 0..15
        #pragma unroll
        for (int ntl = 0; ntl < 2; ntl++) {
            const int nt = 2 * h + ntl;
            #pragma unroll
            for (int mt = 0; mt < 4; mt++)
                #pragma unroll
                for (int e = 0; e < 4; e++) {
                    const int ml = wm * 64 + mt * 16 + gid + (e >> 1) * 8;
                    const int cl = wn * 16 + ntl * 8 + 2 * tig + (e & 1);
                    stage[ml * STG_STRIDE + cl] = acc[mt][nt][e];
                }
        }
        __syncthreads();

        // write: warp handles 16 rows; lanes cover 2x16-float contiguous runs
        for (int r = 0; r < 16; r++) {
            const int ml = wid * 16 + r;
            const int m  = m0 + ml;
            if (m < Mtot) {
                const int b  = m / S;
                const int s  = m - b * S;
                const int yy = s / nx;
                const int xx = s - yy * nx;
                const float fxx = (float)xx - 0.5f;
                const float fyy = (float)yy - 0.5f;
                const size_t base = ((size_t)b * (size_t)total_rows + (size_t)row_off + (size_t)s) * 85u;
                #pragma unroll
                for (int half = 0; half < 2; half++) {
                    const int cl = half * 32 + lane;
                    const int n  = n0 + ((cl >> 4) << 5) + 16 * h + (cl & 15);
                    if (n < 255) {
                        float v  = stage[ml * STG_STRIDE + cl] + bias_s[n];
                        float sg = 1.f / (1.f + __expf(-v));
                        int a = (n >= 170) ? 2 : ((n >= 85) ? 1 : 0);
                        int c = n - a * 85;
                        float o;
                        if (c == 0)      o = (2.f * sg + fxx) * strd;
                        else if (c == 1) o = (2.f * sg + fyy) * strd;
                        else if (c == 2) { float t = 2.f * sg; o = t * t * aw[a]; }
                        else if (c == 3) { float t = 2.f * sg; o = t * t * ah[a]; }
                        else             o = sg;
                        out[base + (size_t)a * sS85 + (size_t)c] = o;
                    }
                }
            }
        }
        __syncthreads();
    }
}

extern "C" void kernel_launch(void* const* d_in, const int* in_sizes, int n_in,
                              void* d_out, int out_size)
{
    const float* p0 = (const float*)d_in[0];
    const float* p1 = (const float*)d_in[1];
    const float* p2 = (const float*)d_in[2];
    const float* w0 = (const float*)d_in[3];
    const float* b0 = (const float*)d_in[4];
    const float* w1 = (const float*)d_in[5];
    const float* b1 = (const float*)d_in[6];
    const float* w2 = (const float*)d_in[7];
    const float* b2 = (const float*)d_in[8];
    const float* anchors = (const float*)d_in[9];
    float* out = (float*)d_out;

    const int bs = in_sizes[0] / (256 * 80 * 80);
    const int t2 = (bs * 400  + 127) / 128;
    const int t1 = (bs * 1600 + 127) / 128;
    const int t0 = (bs * 6400 + 127) / 128;
    const int grid = 2 * (t0 + t1 + t2);

    yolo_all_kernel<<<grid, 256>>>(p0, p1, p2, w0, w1, w2, b0, b1, b2,
                                   anchors, out, bs, t2, t1);
}

// round 13
// speedup vs baseline: 1.0033x; 1.0033x over previous
#include <cuda_runtime.h>
#include <cuda_bf16.h>
#include <cstdint>

// YOLOv5 detect head, unified bf16 HMMA kernel for all three scales.
// CTA tile 128m x 128n, K chunks of 32, double-buffered SMEM (distance-1:
// LDG->regs before MMA block, STS after), ldmatrix.x4 fragments (row stride
// 5 units, conflict-free), SMEM-staged coalesced decode epilogue.

#define ROWU 5
#define BUFU (128 * ROWU)        // 640 uint4 per buffer
#define BUFBYTES (BUFU * 16)     // 10240
#define OFF_B 20480
#define OFF_BIAS 40960
#define OFF_ANC 41984
#define STG_STRIDE 69            // stage row stride (floats); odd -> conflict-free

__device__ __forceinline__ uint32_t smem_u32(const void* p) {
    uint32_t a;
    asm("{ .reg .u64 t; cvta.to.shared.u64 t, %1; cvt.u32.u64 %0, t; }"
        : "=r"(a) : "l"(p));
    return a;
}
__device__ __forceinline__ uint32_t pack2(float a, float b) {
    __nv_bfloat162 h = __floats2bfloat162_rn(a, b);
    return *reinterpret_cast<uint32_t*>(&h);
}

__global__ __launch_bounds__(256, 2)
void yolo_all_kernel(const float* __restrict__ p0, const float* __restrict__ p1,
                     const float* __restrict__ p2,
                     const float* __restrict__ w0, const float* __restrict__ w1,
                     const float* __restrict__ w2,
                     const float* __restrict__ bb0, const float* __restrict__ bb1,
                     const float* __restrict__ bb2,
                     const float* __restrict__ anchors,
                     float* __restrict__ out,
                     int bs, int t2, int t1)
{
    __shared__ __align__(16) char raw[42048];
    uint4* AsmP   = reinterpret_cast<uint4*>(raw);
    uint4* BsmP   = reinterpret_cast<uint4*>(raw + OFF_B);
    float* bias_s = reinterpret_cast<float*>(raw + OFF_BIAS);
    float* anc_s  = reinterpret_cast<float*>(raw + OFF_ANC);
    float* stage  = reinterpret_cast<float*>(raw);   // reused after mainloop

    const int tid  = threadIdx.x;
    const int lane = tid & 31;
    const int wid  = tid >> 5;
    const int wm   = wid >> 2;     // 0..1
    const int wn   = wid & 3;      // 0..3
    const int gid  = lane >> 2;    // 0..7
    const int tig  = lane & 3;     // 0..3

    // ---- scale dispatch (scale 2 first: deepest K) ----
    int bid = blockIdx.x;
    const float *p, *wmat, *bi, *anc;
    int C, S, nx, row_off;
    float strd;
    if (bid < 2 * t2) {
        p = p2; wmat = w2; bi = bb2; anc = anchors + 12;
        C = 1024; S = 400; nx = 20; strd = 32.f; row_off = 24000;
    } else if (bid < 2 * (t2 + t1)) {
        bid -= 2 * t2;
        p = p1; wmat = w1; bi = bb1; anc = anchors + 6;
        C = 512; S = 1600; nx = 40; strd = 16.f; row_off = 19200;
    } else {
        bid -= 2 * (t2 + t1);
        p = p0; wmat = w0; bi = bb0; anc = anchors;
        C = 256; S = 6400; nx = 80; strd = 8.f; row_off = 0;
    }
    const int m0   = (bid >> 1) << 7;
    const int n0   = (bid & 1) << 7;
    const int Mtot = bs * S;

    if (tid < 255) bias_s[tid] = bi[tid];
    if (tid < 6)   anc_s[tid]  = anc[tid];

    // ---- producer mappings ----
    const int arow = tid & 127;
    const int au   = tid >> 7;                 // units au, au+2
    int am = m0 + arow; if (am >= Mtot) am = Mtot - 1;
    const int ab  = am / S;
    const int as_ = am - ab * S;
    const float* abase = p + (size_t)ab * (size_t)C * (size_t)S + (size_t)as_;

    const int brow = tid & 127;
    const int buu  = tid >> 7;
    const int bng  = n0 + brow;
    const float* bbase = (bng < 255) ? (wmat + (size_t)bng * (size_t)C) : nullptr;

    // ---- loop-invariant ldmatrix addresses ----
    const uint32_t a_sm0 = smem_u32(AsmP);
    const uint32_t b_sm0 = smem_u32(BsmP);
    const int l8 = lane & 7, lg = lane >> 3;
    uint32_t aAddr[4], bAddr[2];
    #pragma unroll
    for (int mt = 0; mt < 4; mt++)
        aAddr[mt] = a_sm0 + ((((wm * 64 + mt * 16 + (lg & 1) * 8 + l8) * ROWU) + (lg >> 1)) << 4);
    #pragma unroll
    for (int pr = 0; pr < 2; pr++)
        bAddr[pr] = b_sm0 + ((((wn * 32 + pr * 16 + (lg >> 1) * 8 + l8) * ROWU) + (lg & 1)) << 4);

    float acc[4][4][4] = {};
    const int nk = C >> 5;

    uint32_t aR[8], bR[8];
    auto loadA = [&](int k0) {
        #pragma unroll
        for (int uu = 0; uu < 2; uu++) {
            const int u = au + uu * 2;
            const float* q = abase + (size_t)(k0 + u * 8) * (size_t)S;
            aR[uu * 4 + 0] = pack2(q[0],               q[(size_t)S]);
            aR[uu * 4 + 1] = pack2(q[2 * (size_t)S],   q[3 * (size_t)S]);
            aR[uu * 4 + 2] = pack2(q[4 * (size_t)S],   q[5 * (size_t)S]);
            aR[uu * 4 + 3] = pack2(q[6 * (size_t)S],   q[7 * (size_t)S]);
        }
    };
    auto loadB = [&](int k0) {
        #pragma unroll
        for (int uu = 0; uu < 2; uu++) {
            const int u = buu + uu * 2;
            if (bbase) {
                float4 x = *reinterpret_cast<const float4*>(bbase + k0 + u * 8);
                float4 y = *reinterpret_cast<const float4*>(bbase + k0 + u * 8 + 4);
                bR[uu * 4 + 0] = pack2(x.x, x.y); bR[uu * 4 + 1] = pack2(x.z, x.w);
                bR[uu * 4 + 2] = pack2(y.x, y.y); bR[uu * 4 + 3] = pack2(y.z, y.w);
            } else {
                bR[uu * 4 + 0] = 0u; bR[uu * 4 + 1] = 0u;
                bR[uu * 4 + 2] = 0u; bR[uu * 4 + 3] = 0u;
            }
        }
    };
    auto stsAB = [&](int nb) {
        #pragma unroll
        for (int uu = 0; uu < 2; uu++) {
            AsmP[nb * BUFU + arow * ROWU + (au + uu * 2)] =
                make_uint4(aR[uu * 4], aR[uu * 4 + 1], aR[uu * 4 + 2], aR[uu * 4 + 3]);
            BsmP[nb * BUFU + brow * ROWU + (buu + uu * 2)] =
                make_uint4(bR[uu * 4], bR[uu * 4 + 1], bR[uu * 4 + 2], bR[uu * 4 + 3]);
        }
    };

    // ---- prologue: fill buffer 0 ----
    loadA(0); loadB(0);
    stsAB(0);
    __syncthreads();

    // ---- main loop (distance-1: LDG before MMA, STS after) ----
    for (int it = 0; it < nk; ++it) {
        const int buf = it & 1;
        const uint32_t boff = (uint32_t)buf * BUFBYTES;
        const bool more = (it + 1 < nk);
        if (more) { loadA((it + 1) << 5); loadB((it + 1) << 5); }

        #pragma unroll
        for (int ks = 0; ks < 2; ks++) {
            uint32_t af[4][4], bf[2][4];
            #pragma unroll
            for (int mt = 0; mt < 4; mt++)
                asm volatile("ldmatrix.sync.aligned.m8n8.x4.shared.b16 {%0,%1,%2,%3}, [%4];"
                             : "=r"(af[mt][0]), "=r"(af[mt][1]), "=r"(af[mt][2]), "=r"(af[mt][3])
                             : "r"(aAddr[mt] + boff + ks * 32));
            #pragma unroll
            for (int pr = 0; pr < 2; pr++)
                asm volatile("ldmatrix.sync.aligned.m8n8.x4.shared.b16 {%0,%1,%2,%3}, [%4];"
                             : "=r"(bf[pr][0]), "=r"(bf[pr][1]), "=r"(bf[pr][2]), "=r"(bf[pr][3])
                             : "r"(bAddr[pr] + boff + ks * 32));
            #pragma unroll
            for (int mt = 0; mt < 4; mt++)
                #pragma unroll
                for (int nt = 0; nt < 4; nt++)
                    asm volatile(
                        "mma.sync.aligned.m16n8k16.row.col.f32.bf16.bf16.f32 "
                        "{%0,%1,%2,%3}, {%4,%5,%6,%7}, {%8,%9}, {%0,%1,%2,%3};"
                        : "+f"(acc[mt][nt][0]), "+f"(acc[mt][nt][1]),
                          "+f"(acc[mt][nt][2]), "+f"(acc[mt][nt][3])
                        : "r"(af[mt][0]), "r"(af[mt][1]), "r"(af[mt][2]), "r"(af[mt][3]),
                          "r"(bf[nt >> 1][(nt & 1) * 2]), "r"(bf[nt >> 1][(nt & 1) * 2 + 1]));
        }

        if (more) stsAB(buf ^ 1);
        __syncthreads();
    }

    // ---- epilogue: SMEM-staged coalesced decode ----
    const float aw[3] = { anc_s[0], anc_s[2], anc_s[4] };
    const float ah[3] = { anc_s[1], anc_s[3], anc_s[5] };
    const size_t sS85 = (size_t)S * 85u;
    const int total_rows = 25200;

    #pragma unroll
    for (int h = 0; h < 2; h++) {
        // stage: warp wn's 16-col half (nt = 2h, 2h+1) -> stage cols wn*16 + 0..15
        #pragma unroll
        for (int ntl = 0; ntl < 2; ntl++) {
            const int nt = 2 * h + ntl;
            #pragma unroll
            for (int mt = 0; mt < 4; mt++)
                #pragma unroll
                for (int e = 0; e < 4; e++) {
                    const int ml = wm * 64 + mt * 16 + gid + (e >> 1) * 8;
                    const int cl = wn * 16 + ntl * 8 + 2 * tig + (e & 1);
                    stage[ml * STG_STRIDE + cl] = acc[mt][nt][e];
                }
        }
        __syncthreads();

        // write: warp handles 16 rows; lanes cover 2x16-float contiguous runs
        for (int r = 0; r < 16; r++) {
            const int ml = wid * 16 + r;
            const int m  = m0 + ml;
            if (m < Mtot) {
                const int b  = m / S;
                const int s  = m - b * S;
                const int yy = s / nx;
                const int xx = s - yy * nx;
                const float fxx = (float)xx - 0.5f;
                const float fyy = (float)yy - 0.5f;
                const size_t base = ((size_t)b * (size_t)total_rows + (size_t)row_off + (size_t)s) * 85u;
                #pragma unroll
                for (int half = 0; half < 2; half++) {
                    const int cl = half * 32 + lane;
                    const int n  = n0 + ((cl >> 4) << 5) + 16 * h + (cl & 15);
                    if (n < 255) {
                        float v  = stage[ml * STG_STRIDE + cl] + bias_s[n];
                        float sg = 1.f / (1.f + __expf(-v));
                        int a = (n >= 170) ? 2 : ((n >= 85) ? 1 : 0);
                        int c = n - a * 85;
                        float o;
                        if (c == 0)      o = (2.f * sg + fxx) * strd;
                        else if (c == 1) o = (2.f * sg + fyy) * strd;
                        else if (c == 2) { float t = 2.f * sg; o = t * t * aw[a]; }
                        else if (c == 3) { float t = 2.f * sg; o = t * t * ah[a]; }
                        else             o = sg;
                        out[base + (size_t)a * sS85 + (size_t)c] = o;
                    }
                }
            }
        }
        __syncthreads();
    }
}

extern "C" void kernel_launch(void* const* d_in, const int* in_sizes, int n_in,
                              void* d_out, int out_size)
{
    const float* p0 = (const float*)d_in[0];
    const float* p1 = (const float*)d_in[1];
    const float* p2 = (const float*)d_in[2];
    const float* w0 = (const float*)d_in[3];
    const float* b0 = (const float*)d_in[4];
    const float* w1 = (const float*)d_in[5];
    const float* b1 = (const float*)d_in[6];
    const float* w2 = (const float*)d_in[7];
    const float* b2 = (const float*)d_in[8];
    const float* anchors = (const float*)d_in[9];
    float* out = (float*)d_out;

    const int bs = in_sizes[0] / (256 * 80 * 80);
    const int t2 = (bs * 400  + 127) / 128;
    const int t1 = (bs * 1600 + 127) / 128;
    const int t0 = (bs * 6400 + 127) / 128;
    const int grid = 2 * (t0 + t1 + t2);

    yolo_all_kernel<<<grid, 256>>>(p0, p1, p2, w0, w1, w2, b0, b1, b2,
                                   anchors, out, bs, t2, t1);
}

// round 14
// speedup vs baseline: 1.2740x; 1.2697x over previous
#include <cuda_runtime.h>
#include <cstdint>

// YOLOv5 detect head, unified tf32 MMA kernel (mma.sync.m16n8k8.tf32) for all
// three scales. CTA tile 128m x 128n, K chunks of 32, 3-stage cp.async pipeline
// (GMEM->SMEM fp32, no register staging, no conversions). Padded SMEM:
//   A[k][m] stride 136 words, B[n][k] stride 36 words -> conflict-free frags.
// Scattered direct-store decode epilogue (proven faster than staged).

#define A_STRIDE 136                       // words per A k-row (128 data + 8 pad)
#define B_STRIDE 36                        // words per B n-row (32 data + 4 pad)
#define A_STAGE_BYTES (32 * A_STRIDE * 4)  // 17408
#define B_STAGE_BYTES (128 * B_STRIDE * 4) // 18432
#define STAGE_BYTES (A_STAGE_BYTES + B_STAGE_BYTES)  // 35840
#define NSTAGE 3
#define DSMEM_BYTES (NSTAGE * STAGE_BYTES)           // 107520

__device__ __forceinline__ uint32_t smem_u32(const void* p) {
    uint32_t a;
    asm("{ .reg .u64 t; cvta.to.shared.u64 t, %1; cvt.u32.u64 %0, t; }"
        : "=r"(a) : "l"(p));
    return a;
}
__device__ __forceinline__ void cp16(uint32_t saddr, const void* gaddr) {
    asm volatile("cp.async.cg.shared.global [%0], [%1], 16;"
                 :: "r"(saddr), "l"(gaddr) : "memory");
}

__global__ __launch_bounds__(256, 2)
void yolo_tf32_kernel(const float* __restrict__ p0, const float* __restrict__ p1,
                      const float* __restrict__ p2,
                      const float* __restrict__ w0, const float* __restrict__ w1,
                      const float* __restrict__ w2,
                      const float* __restrict__ bb0, const float* __restrict__ bb1,
                      const float* __restrict__ bb2,
                      const float* __restrict__ anchors,
                      float* __restrict__ out,
                      int bs, int t2, int t1)
{
    extern __shared__ __align__(16) char dsm[];
    __shared__ float bias_s[256];
    __shared__ float anc_s[8];

    const int tid  = threadIdx.x;
    const int lane = tid & 31;
    const int wid  = tid >> 5;
    const int wm   = wid >> 2;     // 0..1
    const int wn   = wid & 3;      // 0..3
    const int gid  = lane >> 2;    // 0..7
    const int tig  = lane & 3;     // 0..3

    // ---- scale dispatch (scale 2 first: deepest K) ----
    int bid = blockIdx.x;
    const float *p, *wmat, *bi, *anc;
    int C, S, nx, row_off;
    float strd;
    if (bid < 2 * t2) {
        p = p2; wmat = w2; bi = bb2; anc = anchors + 12;
        C = 1024; S = 400; nx = 20; strd = 32.f; row_off = 24000;
    } else if (bid < 2 * (t2 + t1)) {
        bid -= 2 * t2;
        p = p1; wmat = w1; bi = bb1; anc = anchors + 6;
        C = 512; S = 1600; nx = 40; strd = 16.f; row_off = 19200;
    } else {
        bid -= 2 * (t2 + t1);
        p = p0; wmat = w0; bi = bb0; anc = anchors;
        C = 256; S = 6400; nx = 80; strd = 8.f; row_off = 0;
    }
    const int m0   = (bid >> 1) << 7;
    const int n0   = (bid & 1) << 7;
    const int Mtot = bs * S;

    if (tid < 255) bias_s[tid] = bi[tid];
    if (tid < 6)   anc_s[tid]  = anc[tid];

    const uint32_t smem_base = smem_u32(dsm);

    // ---- producer mappings (cp.async) ----
    // A tile: 32 k-rows x 128 m (fp32). op q = o*256+tid: k = q>>5, m4 = (q&31)*4
    const int a_mloc = (tid & 31) * 4;          // fixed per thread
    const int a_kb   = tid >> 5;                // k = a_kb + o*8
    int pm = m0 + a_mloc;
    if (pm > Mtot - 4) pm = Mtot - 4;
    const int ab  = pm / S;
    const int as_ = pm - ab * S;
    const float* aG = p + ((size_t)ab * (size_t)C) * (size_t)S + (size_t)as_;
    // B tile: 128 n-rows x 32 k. op q: n = q>>3, k16 = (q&7)*4
    const int b_nloc = tid >> 3;                // n = b_nloc + o*32
    const int b_kloc = (tid & 7) * 4;

    // ---- consumer (fragment) base offsets, bytes relative to stage base ----
    const uint32_t aFragOff = (uint32_t)((tig * A_STRIDE + wm * 64 + gid) * 4);
    const uint32_t bFragOff = (uint32_t)(A_STAGE_BYTES +
                              ((wn * 32 + gid) * B_STRIDE + tig) * 4);

    float acc[4][4][4] = {};
    const int nk = C >> 5;

    auto issue = [&](int stage, int chunk) {
        const uint32_t sb = smem_base + (uint32_t)stage * STAGE_BYTES;
        const int kc0 = chunk << 5;
        #pragma unroll
        for (int o = 0; o < 4; o++) {
            const int k = a_kb + o * 8;
            cp16(sb + (uint32_t)((k * A_STRIDE + a_mloc) * 4),
                 aG + (size_t)(kc0 + k) * (size_t)S);
        }
        #pragma unroll
        for (int o = 0; o < 4; o++) {
            const int n  = b_nloc + o * 32;
            int ng = n0 + n; if (ng > 254) ng = 254;
            cp16(sb + (uint32_t)(A_STAGE_BYTES + (n * B_STRIDE + b_kloc) * 4),
                 wmat + (size_t)ng * (size_t)C + (size_t)(kc0 + b_kloc));
        }
        asm volatile("cp.async.commit_group;" ::: "memory");
    };

    // ---- prologue: stages 0,1 in flight ----
    issue(0, 0);
    issue(1, 1);

    // ---- main loop ----
    for (int it = 0; it < nk; ++it) {
        asm volatile("cp.async.wait_group 1;" ::: "memory");
        __syncthreads();
        if (it + 2 < nk) issue((it + 2) % NSTAGE, it + 2);
        else             asm volatile("cp.async.commit_group;" ::: "memory");

        const char* stg = dsm + (size_t)(it % NSTAGE) * STAGE_BYTES;
        #pragma unroll
        for (int ks = 0; ks < 4; ks++) {
            const char* Ak = stg + aFragOff + ks * (8 * A_STRIDE * 4);
            const char* Bk = stg + bFragOff + ks * 32;
            uint32_t af[4][4], bf[4][2];
            #pragma unroll
            for (int mt = 0; mt < 4; mt++) {
                af[mt][0] = *reinterpret_cast<const uint32_t*>(Ak + mt * 64);
                af[mt][1] = *reinterpret_cast<const uint32_t*>(Ak + mt * 64 + 32);
                af[mt][2] = *reinterpret_cast<const uint32_t*>(Ak + 4 * A_STRIDE * 4 + mt * 64);
                af[mt][3] = *reinterpret_cast<const uint32_t*>(Ak + 4 * A_STRIDE * 4 + mt * 64 + 32);
            }
            #pragma unroll
            for (int nt = 0; nt < 4; nt++) {
                float r0 = *reinterpret_cast<const float*>(Bk + nt * (8 * B_STRIDE * 4));
                float r1 = *reinterpret_cast<const float*>(Bk + nt * (8 * B_STRIDE * 4) + 16);
                asm("cvt.rna.tf32.f32 %0, %1;" : "=r"(bf[nt][0]) : "f"(r0));
                asm("cvt.rna.tf32.f32 %0, %1;" : "=r"(bf[nt][1]) : "f"(r1));
            }
            #pragma unroll
            for (int mt = 0; mt < 4; mt++)
                #pragma unroll
                for (int nt = 0; nt < 4; nt++)
                    asm volatile(
                        "mma.sync.aligned.m16n8k8.row.col.f32.tf32.tf32.f32 "
                        "{%0,%1,%2,%3}, {%4,%5,%6,%7}, {%8,%9}, {%0,%1,%2,%3};"
                        : "+f"(acc[mt][nt][0]), "+f"(acc[mt][nt][1]),
                          "+f"(acc[mt][nt][2]), "+f"(acc[mt][nt][3])
                        : "r"(af[mt][0]), "r"(af[mt][1]), "r"(af[mt][2]), "r"(af[mt][3]),
                          "r"(bf[nt][0]), "r"(bf[nt][1]));
        }
    }

    // ---- epilogue: bias + sigmoid + decode + scattered store (round-7 style) ----
    const float aw[3] = { anc_s[0], anc_s[2], anc_s[4] };
    const float ah[3] = { anc_s[1], anc_s[3], anc_s[5] };
    const size_t sS85 = (size_t)S * 85u;
    const int total_rows = 25200;

    #pragma unroll
    for (int mt = 0; mt < 4; mt++) {
        #pragma unroll
        for (int half = 0; half < 2; half++) {
            const int m = m0 + wm * 64 + mt * 16 + gid + half * 8;
            if (m >= Mtot) continue;
            const int b  = m / S;
            const int s  = m - b * S;
            const int yy = s / nx;
            const int xx = s - yy * nx;
            const float fxx = (float)xx - 0.5f;
            const float fyy = (float)yy - 0.5f;
            const size_t base = ((size_t)b * (size_t)total_rows + (size_t)row_off + (size_t)s) * 85u;
            #pragma unroll
            for (int nt = 0; nt < 4; nt++) {
                const int n = n0 + wn * 32 + nt * 8 + 2 * tig;
                #pragma unroll
                for (int e = 0; e < 2; e++) {
                    const int nn = n + e;
                    if (nn >= 255) continue;
                    float v  = acc[mt][nt][half * 2 + e] + bias_s[nn];
                    float sg = 1.f / (1.f + __expf(-v));
                    int a = (nn >= 170) ? 2 : ((nn >= 85) ? 1 : 0);
                    int c = nn - a * 85;
                    float o;
                    if (c == 0)      o = (2.f * sg + fxx) * strd;
                    else if (c == 1) o = (2.f * sg + fyy) * strd;
                    else if (c == 2) { float t = 2.f * sg; o = t * t * aw[a]; }
                    else if (c == 3) { float t = 2.f * sg; o = t * t * ah[a]; }
                    else             o = sg;
                    out[base + (size_t)a * sS85 + (size_t)c] = o;
                }
            }
        }
    }
}

extern "C" void kernel_launch(void* const* d_in, const int* in_sizes, int n_in,
                              void* d_out, int out_size)
{
    const float* p0 = (const float*)d_in[0];
    const float* p1 = (const float*)d_in[1];
    const float* p2 = (const float*)d_in[2];
    const float* w0 = (const float*)d_in[3];
    const float* b0 = (const float*)d_in[4];
    const float* w1 = (const float*)d_in[5];
    const float* b1 = (const float*)d_in[6];
    const float* w2 = (const float*)d_in[7];
    const float* b2 = (const float*)d_in[8];
    const float* anchors = (const float*)d_in[9];
    float* out = (float*)d_out;

    static int configured = 0;
    if (!configured) {
        cudaFuncSetAttribute(yolo_tf32_kernel,
                             cudaFuncAttributeMaxDynamicSharedMemorySize, DSMEM_BYTES);
        configured = 1;
    }

    const int bs = in_sizes[0] / (256 * 80 * 80);
    const int t2 = (bs * 400  + 127) / 128;
    const int t1 = (bs * 1600 + 127) / 128;
    const int t0 = (bs * 6400 + 127) / 128;
    const int grid = 2 * (t0 + t1 + t2);

    yolo_tf32_kernel<<<grid, 256, DSMEM_BYTES>>>(p0, p1, p2, w0, w1, w2,
                                                 b0, b1, b2, anchors, out,
                                                 bs, t2, t1);
}

// round 15
// speedup vs baseline: 1.4435x; 1.1331x over previous
#include <cuda_runtime.h>
#include <cuda_bf16.h>
#include <cstdint>

// YOLOv5 detect head, two-kernel scheme:
//  K1: stream-convert p0/p1/p2/w* fp32 -> bf16 into __device__ scratch (layout kept).
//  K2: unified bf16 GEMM (mma.m16n8k16) for all scales. CTA 128m x 128n, K chunks
//      of 32, 4-stage cp.async pipeline straight from bf16 gmem (no cvt in loop),
//      ldmatrix fragments (A: x4.trans from [k][m] 272B rows; B: x4 from [n][k]
//      80B rows; both conflict-free), scattered decode epilogue (proven best).

#define A_ROW_B 272                    // 128 bf16 (256B) + 16B pad
#define A_ST_BYTES (32 * A_ROW_B)      // 8704
#define B_ROW_B 80                     // 32 bf16 (64B) + 16B pad
#define B_ST_BYTES (128 * B_ROW_B)     // 10240
#define STAGE_B (A_ST_BYTES + B_ST_BYTES)  // 18944
#define NST 4
#define DSMEM (NST * STAGE_B)          // 75776

__device__ __nv_bfloat16 g_pb[45875200];   // bs<=16: p0|p1|p2 bf16
__device__ __nv_bfloat16 g_wb[456960];     // w0|w1|w2 bf16

__device__ __forceinline__ uint32_t smem_u32(const void* p) {
    uint32_t a;
    asm("{ .reg .u64 t; cvta.to.shared.u64 t, %1; cvt.u32.u64 %0, t; }"
        : "=r"(a) : "l"(p));
    return a;
}
__device__ __forceinline__ void cp16(uint32_t saddr, const void* gaddr) {
    asm volatile("cp.async.cg.shared.global [%0], [%1], 16;"
                 :: "r"(saddr), "l"(gaddr) : "memory");
}
__device__ __forceinline__ uint32_t pack2(float a, float b) {
    __nv_bfloat162 h = __floats2bfloat162_rn(a, b);
    return *reinterpret_cast<uint32_t*>(&h);
}

// ---------------- K1: fp32 -> bf16 convert ----------------
__global__ void cvt_kernel(const float* __restrict__ p0, const float* __restrict__ p1,
                           const float* __restrict__ p2,
                           const float* __restrict__ w0, const float* __restrict__ w1,
                           const float* __restrict__ w2, int bs)
{
    const size_t N0 = (size_t)bs * 409600;   // p0 float4 count (1638400/4 per b)
    const size_t N1 = (size_t)bs * 204800;
    const size_t N2 = (size_t)bs * 102400;
    const size_t NW0 = 16320, NW1 = 32640, NW2 = 65280;
    size_t i = (size_t)blockIdx.x * blockDim.x + threadIdx.x;
    const float* src; __nv_bfloat16* dst; size_t loc;
    if (i < N0)                 { src = p0; dst = g_pb;                       loc = i; }
    else if (i < N0+N1)         { src = p1; dst = g_pb + N0*4;                loc = i-N0; }
    else if (i < N0+N1+N2)      { src = p2; dst = g_pb + (N0+N1)*4;           loc = i-N0-N1; }
    else if (i < N0+N1+N2+NW0)  { src = w0; dst = g_wb;                       loc = i-N0-N1-N2; }
    else if (i < N0+N1+N2+NW0+NW1) { src = w1; dst = g_wb + 65280;            loc = i-N0-N1-N2-NW0; }
    else if (i < N0+N1+N2+NW0+NW1+NW2) { src = w2; dst = g_wb + 195840;       loc = i-N0-N1-N2-NW0-NW1; }
    else return;
    float4 v = reinterpret_cast<const float4*>(src)[loc];
    uint2 o;
    o.x = pack2(v.x, v.y);
    o.y = pack2(v.z, v.w);
    reinterpret_cast<uint2*>(dst)[loc] = o;
}

// ---------------- K2: bf16 GEMM + decode ----------------
__global__ __launch_bounds__(256, 2)
void yolo_bf16_kernel(const float* __restrict__ bb0, const float* __restrict__ bb1,
                      const float* __restrict__ bb2,
                      const float* __restrict__ anchors,
                      float* __restrict__ out,
                      int bs, int t2, int t1)
{
    extern __shared__ __align__(16) char dsm[];
    __shared__ float bias_s[256];
    __shared__ float anc_s[8];

    const int tid  = threadIdx.x;
    const int lane = tid & 31;
    const int wid  = tid >> 5;
    const int wm   = wid >> 2;     // 0..1
    const int wn   = wid & 3;      // 0..3
    const int gid  = lane >> 2;    // 0..7
    const int tig  = lane & 3;     // 0..3

    // ---- scale dispatch (scale 2 first: deepest K) ----
    int bid = blockIdx.x;
    const __nv_bfloat16 *p, *wmat;
    const float *bi, *anc;
    int C, S, nx, row_off;
    float strd;
    const size_t o1 = (size_t)bs * 1638400;
    const size_t o2 = o1 + (size_t)bs * 819200;
    if (bid < 2 * t2) {
        p = g_pb + o2; wmat = g_wb + 195840; bi = bb2; anc = anchors + 12;
        C = 1024; S = 400; nx = 20; strd = 32.f; row_off = 24000;
    } else if (bid < 2 * (t2 + t1)) {
        bid -= 2 * t2;
        p = g_pb + o1; wmat = g_wb + 65280; bi = bb1; anc = anchors + 6;
        C = 512; S = 1600; nx = 40; strd = 16.f; row_off = 19200;
    } else {
        bid -= 2 * (t2 + t1);
        p = g_pb; wmat = g_wb; bi = bb0; anc = anchors;
        C = 256; S = 6400; nx = 80; strd = 8.f; row_off = 0;
    }
    const int m0   = (bid >> 1) << 7;
    const int n0   = (bid & 1) << 7;
    const int Mtot = bs * S;

    if (tid < 255) bias_s[tid] = bi[tid];
    if (tid < 6)   anc_s[tid]  = anc[tid];

    const uint32_t smem_base = smem_u32(dsm);

    // ---- producer mappings ----
    // A: 32 k-rows x 256B; op(o,tid): k = (tid>>4)+o*16, m8 = (tid&15)*8
    const int a_m8 = (tid & 15) * 8;
    const int a_kb = tid >> 4;
    int pm = m0 + a_m8;
    if (pm > Mtot - 8) pm = Mtot - 8;
    const int ab  = pm / S;
    const int as_ = pm - ab * S;
    const __nv_bfloat16* aG = p + ((size_t)ab * (size_t)C) * (size_t)S + (size_t)as_;
    // B: 128 n-rows x 64B; op(o,tid): n = (tid>>2)+o*64, k8 = (tid&3)*8
    const int b_nb = tid >> 2;
    const int b_k8 = (tid & 3) * 8;

    // ---- ldmatrix addresses ----
    // A (.trans, [k][m] 272B rows): krow = (lane&7) + ((lane>>4)&1)*8 ; mcol = lane&8
    const int a_krow = (lane & 7) + ((lane >> 4) & 1) * 8;
    const int a_mcol = lane & 8;
    uint32_t aAddr[4];
    #pragma unroll
    for (int mt = 0; mt < 4; mt++)
        aAddr[mt] = smem_base + (uint32_t)(a_krow * A_ROW_B
                  + (wm * 64 + mt * 16 + a_mcol) * 2);
    // B (non-trans, [n][k] 80B rows): round-7 tile order (t0 n-lo k-lo, t1 n-lo k-hi, ...)
    const int b_row4 = ((lane >> 4) & 1) * 8 + (lane & 7);
    const int b_koff = ((lane >> 3) & 1) * 16;   // bytes
    uint32_t bAddr[2];
    #pragma unroll
    for (int pr = 0; pr < 2; pr++)
        bAddr[pr] = smem_base + A_ST_BYTES
                  + (uint32_t)((wn * 32 + pr * 16 + b_row4) * B_ROW_B) + b_koff;

    float acc[4][4][4] = {};
    const int nk = C >> 5;

    auto issue = [&](int stage, int chunk) {
        const uint32_t sb = smem_base + (uint32_t)stage * STAGE_B;
        const int kc0 = chunk << 5;
        #pragma unroll
        for (int o = 0; o < 2; o++) {
            const int k = a_kb + o * 16;
            cp16(sb + (uint32_t)(k * A_ROW_B + a_m8 * 2),
                 aG + (size_t)(kc0 + k) * (size_t)S);
        }
        #pragma unroll
        for (int o = 0; o < 2; o++) {
            const int n = b_nb + o * 64;
            int ng = n0 + n; if (ng > 254) ng = 254;
            cp16(sb + (uint32_t)(A_ST_BYTES + n * B_ROW_B + b_k8 * 2),
                 wmat + (size_t)ng * (size_t)C + (size_t)(kc0 + b_k8));
        }
        asm volatile("cp.async.commit_group;" ::: "memory");
    };

    // ---- prologue: 3 stages in flight ----
    issue(0, 0);
    issue(1, 1);
    issue(2, 2);

    // ---- main loop ----
    for (int it = 0; it < nk; ++it) {
        asm volatile("cp.async.wait_group 2;" ::: "memory");
        __syncthreads();
        if (it + 3 < nk) issue((it + 3) & 3, it + 3);
        else             asm volatile("cp.async.commit_group;" ::: "memory");

        const uint32_t soff = (uint32_t)(it & 3) * STAGE_B;
        #pragma unroll
        for (int ks = 0; ks < 2; ks++) {
            uint32_t af[4][4], bf[2][4];
            #pragma unroll
            for (int mt = 0; mt < 4; mt++)
                asm volatile("ldmatrix.sync.aligned.m8n8.x4.trans.shared.b16 {%0,%1,%2,%3}, [%4];"
                             : "=r"(af[mt][0]), "=r"(af[mt][1]), "=r"(af[mt][2]), "=r"(af[mt][3])
                             : "r"(aAddr[mt] + soff + ks * (16 * A_ROW_B)));
            #pragma unroll
            for (int pr = 0; pr < 2; pr++)
                asm volatile("ldmatrix.sync.aligned.m8n8.x4.shared.b16 {%0,%1,%2,%3}, [%4];"
                             : "=r"(bf[pr][0]), "=r"(bf[pr][1]), "=r"(bf[pr][2]), "=r"(bf[pr][3])
                             : "r"(bAddr[pr] + soff + ks * 32));
            #pragma unroll
            for (int mt = 0; mt < 4; mt++)
                #pragma unroll
                for (int nt = 0; nt < 4; nt++)
                    asm volatile(
                        "mma.sync.aligned.m16n8k16.row.col.f32.bf16.bf16.f32 "
                        "{%0,%1,%2,%3}, {%4,%5,%6,%7}, {%8,%9}, {%0,%1,%2,%3};"
                        : "+f"(acc[mt][nt][0]), "+f"(acc[mt][nt][1]),
                          "+f"(acc[mt][nt][2]), "+f"(acc[mt][nt][3])
                        : "r"(af[mt][0]), "r"(af[mt][1]), "r"(af[mt][2]), "r"(af[mt][3]),
                          "r"(bf[nt >> 1][(nt & 1) * 2]), "r"(bf[nt >> 1][(nt & 1) * 2 + 1]));
        }
    }

    // ---- epilogue: bias + sigmoid + decode + scattered store ----
    const float aw[3] = { anc_s[0], anc_s[2], anc_s[4] };
    const float ah[3] = { anc_s[1], anc_s[3], anc_s[5] };
    const size_t sS85 = (size_t)S * 85u;
    const int total_rows = 25200;

    #pragma unroll
    for (int mt = 0; mt < 4; mt++) {
        #pragma unroll
        for (int half = 0; half < 2; half++) {
            const int m = m0 + wm * 64 + mt * 16 + gid + half * 8;
            if (m >= Mtot) continue;
            const int b  = m / S;
            const int s  = m - b * S;
            const int yy = s / nx;
            const int xx = s - yy * nx;
            const float fxx = (float)xx - 0.5f;
            const float fyy = (float)yy - 0.5f;
            const size_t base = ((size_t)b * (size_t)total_rows + (size_t)row_off + (size_t)s) * 85u;
            #pragma unroll
            for (int nt = 0; nt < 4; nt++) {
                const int n = n0 + wn * 32 + nt * 8 + 2 * tig;
                #pragma unroll
                for (int e = 0; e < 2; e++) {
                    const int nn = n + e;
                    if (nn >= 255) continue;
                    float v  = acc[mt][nt][half * 2 + e] + bias_s[nn];
                    float sg = 1.f / (1.f + __expf(-v));
                    int a = (nn >= 170) ? 2 : ((nn >= 85) ? 1 : 0);
                    int c = nn - a * 85;
                    float o;
                    if (c == 0)      o = (2.f * sg + fxx) * strd;
                    else if (c == 1) o = (2.f * sg + fyy) * strd;
                    else if (c == 2) { float t = 2.f * sg; o = t * t * aw[a]; }
                    else if (c == 3) { float t = 2.f * sg; o = t * t * ah[a]; }
                    else             o = sg;
                    out[base + (size_t)a * sS85 + (size_t)c] = o;
                }
            }
        }
    }
}

extern "C" void kernel_launch(void* const* d_in, const int* in_sizes, int n_in,
                              void* d_out, int out_size)
{
    const float* p0 = (const float*)d_in[0];
    const float* p1 = (const float*)d_in[1];
    const float* p2 = (const float*)d_in[2];
    const float* w0 = (const float*)d_in[3];
    const float* b0 = (const float*)d_in[4];
    const float* w1 = (const float*)d_in[5];
    const float* b1 = (const float*)d_in[6];
    const float* w2 = (const float*)d_in[7];
    const float* b2 = (const float*)d_in[8];
    const float* anchors = (const float*)d_in[9];
    float* out = (float*)d_out;

    cudaFuncSetAttribute(yolo_bf16_kernel,
                         cudaFuncAttributeMaxDynamicSharedMemorySize, DSMEM);

    const int bs = in_sizes[0] / (256 * 80 * 80);

    // K1: convert
    {
        size_t total4 = (size_t)bs * (409600 + 204800 + 102400) + 16320 + 32640 + 65280;
        int grid = (int)((total4 + 255) / 256);
        cvt_kernel<<<grid, 256>>>(p0, p1, p2, w0, w1, w2, bs);
    }

    // K2: GEMM + decode
    {
        const int t2 = (bs * 400  + 127) / 128;
        const int t1 = (bs * 1600 + 127) / 128;
        const int t0 = (bs * 6400 + 127) / 128;
        const int grid = 2 * (t0 + t1 + t2);
        yolo_bf16_kernel<<<grid, 256, DSMEM>>>(b0, b1, b2, anchors, out, bs, t2, t1);
    }
}